// round 14
// baseline (speedup 1.0000x reference)
#include <cuda_runtime.h>

#define NS   48000
#define NIN  400
#define NSEG 401      // head(60) + 399 interior(120) + tail(60)
#define NB   16
#define NM   64
#define NROWS (NB*NM)
#define PREP_BLOCKS 1024

// Scratch (allocation-free)
__device__ float2 g_Bp[(size_t)NROWS * NSEG];  // per-(row,seg) phase base {radians, turns}
__device__ double g_FT[NSEG];                  // per-segment frac totals (for scan)
__device__ float4 g_F1q[NSEG * 30];            // frac-cumsum table (float4-packed, 120/seg)

// Producer-count sync state (replay-safe: last exiting block resets both).
__device__ int g_done;   // phase-A segment completions (0..NSEG)
__device__ int g_exit;   // blocks past the spin (0..PREP_BLOCKS)

// Exact replica of the reference's fp32 position/frac computation.
__device__ __forceinline__ float ref_frac(int j) {
    const float SCALE = 400.0f / 48000.0f;   // fl32(1/120)
    float pos = __fsub_rn(__fmul_rn(__fadd_rn((float)j, 0.5f), SCALE), 0.5f);
    pos = fminf(fmaxf(pos, 0.0f), 399.0f);
    float fi = floorf(pos);
    return __fsub_rn(pos, fi);               // exact (Sterbenz)
}

// Prep kernel: Phase A (frac table; warp 0 of blocks 0..400, one segment each)
// -> producer-count spin (401 atomic arrivals, spin-read release) ->
// Phase B (block-per-row fp64 scan + mod-2pi base reduction).
__global__ void __launch_bounds__(128, 8)
prep_kernel(const float* __restrict__ params) {
    int tid  = threadIdx.x;
    int lane = tid & 31, wp = tid >> 5;

    // ---- Phase A: warp 0 of block s computes segment s ----------------------
    if (wp == 0 && blockIdx.x < NSEG) {
        int s = blockIdx.x;
        int start = (s == 0) ? 0 : 60 + (s - 1) * 120;
        int m0 = lane * 4;
        double s0 = (double)ref_frac(start + m0);
        double s1 = s0 + (double)ref_frac(start + m0 + 1);
        double s2 = s1 + (double)ref_frac(start + m0 + 2);
        double s3 = s2 + (double)ref_frac(start + m0 + 3);
        double T = s3, inc = T;
        #pragma unroll
        for (int off = 1; off < 32; off <<= 1) {
            double n = __shfl_up_sync(0xFFFFFFFFu, inc, off);
            if (lane >= off) inc += n;
        }
        double base = inc - T;            // exclusive prefix of lane totals
        if (m0 < 120)
            g_F1q[s * 30 + lane] = make_float4((float)(base + s0), (float)(base + s1),
                                               (float)(base + s2), (float)(base + s3));
        if (lane == 30) g_FT[s] = base;   // sum over samples 0..119
        __threadfence();
        if (lane == 0) atomicAdd(&g_done, 1);
    }

    // ---- Wait for all 401 segments (producer-count spin, read-only release)
    if (tid == 0) {
        while (*(volatile int*)&g_done != NSEG) { __nanosleep(20); }
    }
    __syncthreads();
    __threadfence();

    // ---- Phase B: block = row; 128 threads x 4 contiguous values ----------
    {
        int r = blockIdx.x;                 // 0..1023
        int b = r >> 6, mode = r & 63;
        const float* F = params + (size_t)(b * 192 + mode) * 400;  // freqs
        const float* P = F + 128 * 400;                            // phase
        float p0 = P[0];

        double loc[4];
        double run = 0.0;
        #pragma unroll
        for (int i = 0; i < 4; i++) {
            int idx = tid * 4 + i;
            double v = 0.0;
            if (idx == 0) {
                v = 60.0 * (double)F[0];
            } else if (idx <= 399) {
                double f0 = F[idx - 1], f1 = F[idx];
                v = 120.0 * f0 + (f1 - f0) * g_FT[idx];
            }
            run += v;
            loc[i] = run;                     // local inclusive
        }
        // warp scan of thread totals
        double T = run, inc = T;
        #pragma unroll
        for (int off = 1; off < 32; off <<= 1) {
            double n = __shfl_up_sync(0xFFFFFFFFu, inc, off);
            if (lane >= off) inc += n;
        }
        __shared__ double sW[4];
        if (lane == 31) sW[wp] = inc;
        __syncthreads();
        double wbase = 0.0;
        #pragma unroll
        for (int i = 0; i < 3; i++)
            if (i < wp) wbase += sW[i];
        double tbase = wbase + (inc - T);

        #pragma unroll
        for (int i = 0; i < 4; i++) {
            int idx = tid * 4 + i;
            if (idx <= 400) {
                double excl = tbase + (i ? loc[i - 1] : 0.0);
                double tot  = excl + (double)p0;
                double tt   = tot * 0.15915494309189535;   // turns
                double kk   = rint(tt);
                double ft   = tt - kk;                     // [-0.5, 0.5] turns
                g_Bp[(size_t)r * NSEG + idx] =
                    make_float2((float)(ft * 6.283185307179586), (float)ft);
            }
        }
    }

    // ---- Replay-safe reset: last exiting block zeroes the counters ---------
    // (every g_done increment provably precedes any g_exit increment)
    if (tid == 0) {
        int e = atomicAdd(&g_exit, 1);
        if (e == PREP_BLOCKS - 1) {
            g_done = 0;
            __threadfence();
            g_exit = 0;
        }
    }
}

// Synthesis: block=(segment s, batch b), 64 threads, 2 samples/thread.
// Measured-optimal hybrid (R9): 7 of every 32 modes via fma-pipe polynomial
// (turns phase, magic-rint reduce, deg-11 odd minimax), rest via MUFU.
__global__ void __launch_bounds__(64) synth_kernel(const float* __restrict__ params,
                                                   float* __restrict__ out) {
    int s = blockIdx.x, b = blockIdx.y;
    __shared__ float4 md0[64];   // {base_rad, f0_rad, dF_rad, a0}
    __shared__ float4 md1[64];   // {base_trn, f0_trn, dF_trn, da}
    int tid = threadIdx.x;

    {
        int mode = tid;          // 64 threads == 64 modes
        const float* F = params + (size_t)(b * 192 + mode) * 400;
        const float* A = F + 64 * 400;      // channel 1 = amps
        int i  = (s == 0) ? 0 : ((s <= 399) ? s - 1 : 399);
        int i1 = min(i + 1, 399);
        float f0 = F[i];
        float dw = F[i1] - f0;
        float a0 = A[i];
        float da = A[i1] - a0;
        float2 bp = g_Bp[(size_t)(b * 64 + mode) * NSEG + s];
        const float INV2PI_F = 0.15915494f;
        md0[mode] = make_float4(bp.x, f0, dw, a0);
        md1[mode] = make_float4(bp.y, f0 * INV2PI_F, dw * INV2PI_F, da);
    }
    __syncthreads();

    int m = tid;
    if (m >= 60) return;                    // 60 threads x 2 samples = 120
    bool interior = (s != 0 && s != 400);
    int start = (s == 0) ? 0 : 60 + (s - 1) * 120;
    int j0 = start + m;
    int j1 = start + m + 60;

    const float* F1 = (const float*)g_F1q;
    float t1a = (float)(m + 1),  t1b = (float)(m + 61);
    float F1a = F1[s * 120 + m], F1b = F1[s * 120 + m + 60];
    float fra = ref_frac(j0);
    float frb = interior ? ref_frac(j1) : 0.0f;

    const float MAGIC  = 12582912.0f;       // 1.5 * 2^23
    const float TWOPI  = 6.2831853f;
    const float C11 = -2.3889859e-08f;
    const float C9  =  2.7525562e-06f;
    const float C7  = -0.00019840874f;
    const float C5  =  0.0083333310f;
    const float C3  = -0.16666667f;

    float acc_a = 0.0f, acc_b = 0.0f;
#pragma unroll
    for (int k = 0; k < 64; k++) {
        // 7-of-32 poly pattern: {0,5,10,15,20,25,30} per 32 (measured optimum)
        bool poly = ((k & 31) % 5 == 0) && ((k & 31) != 31);
        if (poly) {
            // fma-pipe path: turns + magic reduce + deg-11 odd minimax
            float4 q = md1[k];
            float a0k = md0[k].w, dak = q.w;
            float ph = fmaf(t1a, q.y, q.x); ph = fmaf(F1a, q.z, ph);
            float kr = (ph + MAGIC) - MAGIC;        // rint(ph) in turns
            float r  = (ph - kr) * TWOPI;           // [-pi, pi] radians
            float x2 = r * r;
            float p  = fmaf(C11, x2, C9);
            p = fmaf(p, x2, C7); p = fmaf(p, x2, C5);
            p = fmaf(p, x2, C3); p = fmaf(p, x2, 1.0f);
            float aa = fmaf(dak, fra, a0k);
            acc_a = fmaf(aa * r, p, acc_a);
            float phb = fmaf(t1b, q.y, q.x); phb = fmaf(F1b, q.z, phb);
            float krb = (phb + MAGIC) - MAGIC;
            float rb  = (phb - krb) * TWOPI;
            float xb2 = rb * rb;
            float pb  = fmaf(C11, xb2, C9);
            pb = fmaf(pb, xb2, C7); pb = fmaf(pb, xb2, C5);
            pb = fmaf(pb, xb2, C3); pb = fmaf(pb, xb2, 1.0f);
            float ab = fmaf(dak, frb, a0k);
            acc_b = fmaf(ab * rb, pb, acc_b);
        } else {
            // MUFU path
            float4 q = md0[k];
            float dak = md1[k].w;
            float ph  = fmaf(t1a, q.y, q.x); ph  = fmaf(F1a, q.z, ph);
            float phb = fmaf(t1b, q.y, q.x); phb = fmaf(F1b, q.z, phb);
            float aa = fmaf(dak, fra, q.w);
            float ab = fmaf(dak, frb, q.w);
            acc_a = fmaf(aa, __sinf(ph),  acc_a);
            acc_b = fmaf(ab, __sinf(phb), acc_b);
        }
    }

    out[(size_t)b * NS + j0] = acc_a;
    if (interior) out[(size_t)b * NS + j1] = acc_b;
}

extern "C" void kernel_launch(void* const* d_in, const int* in_sizes, int n_in,
                              void* d_out, int out_size) {
    const float* params = (const float*)d_in[0];
    float* out = (float*)d_out;
    prep_kernel<<<PREP_BLOCKS, 128>>>(params);
    dim3 grid(NSEG, NB);
    synth_kernel<<<grid, 64>>>(params, out);
}

// round 15
// speedup vs baseline: 1.0301x; 1.0301x over previous
#include <cuda_runtime.h>

#define NS   48000
#define NIN  400
#define NSEG 401      // head(60) + 399 interior(120) + tail(60)
#define NB   16
#define NM   64
#define NROWS (NB*NM)
#define PREP_BLOCKS 1024

// Scratch (allocation-free)
__device__ float2 g_Bp[(size_t)NROWS * NSEG];  // per-(row,seg) phase base {radians, turns}
__device__ double g_FT[NSEG];                  // per-segment frac totals (for scan)
__device__ float4 g_F1q[NSEG * 30];            // frac-cumsum table (float4-packed, 120/seg)

// Phase-A completion counter. Incremented to NSEG by prep's 401 segment-warps;
// reset to 0 by synth block (0,0), which runs strictly after prep on the
// stream -> valid for every graph replay, zero reset cost inside prep.
__device__ int g_done;

// Exact replica of the reference's fp32 position/frac computation.
__device__ __forceinline__ float ref_frac(int j) {
    const float SCALE = 400.0f / 48000.0f;   // fl32(1/120)
    float pos = __fsub_rn(__fmul_rn(__fadd_rn((float)j, 0.5f), SCALE), 0.5f);
    pos = fminf(fmaxf(pos, 0.0f), 399.0f);
    float fi = floorf(pos);
    return __fsub_rn(pos, fi);               // exact (Sterbenz)
}

// Prep kernel: Phase A (frac table, warp-per-segment, blocks 0..100) ->
// param-load hoist -> producer-count spin -> Phase B combine + scan.
__global__ void __launch_bounds__(128, 8)
prep_kernel(const float* __restrict__ params) {
    int tid  = threadIdx.x;
    int lane = tid & 31, wp = tid >> 5;

    // ---- Phase A: one warp per segment, blocks 0..100 (404 warps >= 401) ---
    {
        int s = blockIdx.x * 4 + wp;
        if (blockIdx.x <= 100 && s < NSEG) {
            int start = (s == 0) ? 0 : 60 + (s - 1) * 120;
            int m0 = lane * 4;
            double s0 = (double)ref_frac(start + m0);
            double s1 = s0 + (double)ref_frac(start + m0 + 1);
            double s2 = s1 + (double)ref_frac(start + m0 + 2);
            double s3 = s2 + (double)ref_frac(start + m0 + 3);
            double T = s3, inc = T;
            #pragma unroll
            for (int off = 1; off < 32; off <<= 1) {
                double n = __shfl_up_sync(0xFFFFFFFFu, inc, off);
                if (lane >= off) inc += n;
            }
            double base = inc - T;            // exclusive prefix of lane totals
            if (m0 < 120)
                g_F1q[s * 30 + lane] = make_float4((float)(base + s0), (float)(base + s1),
                                                   (float)(base + s2), (float)(base + s3));
            if (lane == 30) g_FT[s] = base;   // sum over samples 0..119
            __threadfence();
            if (lane == 0) atomicAdd(&g_done, 1);
        }
    }

    // ---- Phase B prefetch (independent of phase A): hide L2 latency --------
    int r = blockIdx.x;                 // 0..1023
    int b = r >> 6, mode = r & 63;
    const float* F = params + (size_t)(b * 192 + mode) * 400;  // freqs
    const float* P = F + 128 * 400;                            // phase
    float p0 = P[0];
    float fv[5];                        // F[tid*4-1 .. tid*4+3] clamped
    #pragma unroll
    for (int i = 0; i < 5; i++) {
        int idx = tid * 4 - 1 + i;
        fv[i] = F[min(max(idx, 0), 399)];
    }

    // ---- Wait for all 401 segments (read-only spin release) ----------------
    if (tid == 0) {
        while (*(volatile int*)&g_done != NSEG) { __nanosleep(40); }
    }
    __syncthreads();
    __threadfence();

    // ---- Phase B: combine with g_FT, fp64 scan, mod-2pi reduce -------------
    {
        double loc[4];
        double run = 0.0;
        #pragma unroll
        for (int i = 0; i < 4; i++) {
            int idx = tid * 4 + i;
            double v = 0.0;
            if (idx == 0) {
                v = 60.0 * (double)fv[1];     // F[0]
            } else if (idx <= 399) {
                double f0 = fv[i], f1 = fv[i + 1];
                v = 120.0 * f0 + (f1 - f0) * g_FT[idx];
            }
            run += v;
            loc[i] = run;                     // local inclusive
        }
        // warp scan of thread totals
        double T = run, inc = T;
        #pragma unroll
        for (int off = 1; off < 32; off <<= 1) {
            double n = __shfl_up_sync(0xFFFFFFFFu, inc, off);
            if (lane >= off) inc += n;
        }
        __shared__ double sW[4];
        if (lane == 31) sW[wp] = inc;
        __syncthreads();
        double wbase = 0.0;
        #pragma unroll
        for (int i = 0; i < 3; i++)
            if (i < wp) wbase += sW[i];
        double tbase = wbase + (inc - T);

        #pragma unroll
        for (int i = 0; i < 4; i++) {
            int idx = tid * 4 + i;
            if (idx <= 400) {
                double excl = tbase + (i ? loc[i - 1] : 0.0);
                double tot  = excl + (double)p0;
                double tt   = tot * 0.15915494309189535;   // turns
                double kk   = rint(tt);
                double ft   = tt - kk;                     // [-0.5, 0.5] turns
                g_Bp[(size_t)r * NSEG + idx] =
                    make_float2((float)(ft * 6.283185307179586), (float)ft);
            }
        }
    }
}

// Synthesis: block=(segment s, batch b), 64 threads, 2 samples/thread.
// Measured-optimal hybrid (R9): 7 of every 32 modes via fma-pipe polynomial
// (turns phase, magic-rint reduce, deg-11 odd minimax), rest via MUFU.
__global__ void __launch_bounds__(64) synth_kernel(const float* __restrict__ params,
                                                   float* __restrict__ out) {
    int s = blockIdx.x, b = blockIdx.y;
    __shared__ float4 md0[64];   // {base_rad, f0_rad, dF_rad, a0}
    __shared__ float4 md1[64];   // {base_trn, f0_trn, dF_trn, da}
    int tid = threadIdx.x;

    // Replay-safe reset of the prep counter (prep of the NEXT launch sees 0).
    if (s == 0 && b == 0 && tid == 0) g_done = 0;

    {
        int mode = tid;          // 64 threads == 64 modes
        const float* F = params + (size_t)(b * 192 + mode) * 400;
        const float* A = F + 64 * 400;      // channel 1 = amps
        int i  = (s == 0) ? 0 : ((s <= 399) ? s - 1 : 399);
        int i1 = min(i + 1, 399);
        float f0 = F[i];
        float dw = F[i1] - f0;
        float a0 = A[i];
        float da = A[i1] - a0;
        float2 bp = g_Bp[(size_t)(b * 64 + mode) * NSEG + s];
        const float INV2PI_F = 0.15915494f;
        md0[mode] = make_float4(bp.x, f0, dw, a0);
        md1[mode] = make_float4(bp.y, f0 * INV2PI_F, dw * INV2PI_F, da);
    }
    __syncthreads();

    int m = tid;
    if (m >= 60) return;                    // 60 threads x 2 samples = 120
    bool interior = (s != 0 && s != 400);
    int start = (s == 0) ? 0 : 60 + (s - 1) * 120;
    int j0 = start + m;
    int j1 = start + m + 60;

    const float* F1 = (const float*)g_F1q;
    float t1a = (float)(m + 1),  t1b = (float)(m + 61);
    float F1a = F1[s * 120 + m], F1b = F1[s * 120 + m + 60];
    float fra = ref_frac(j0);
    float frb = interior ? ref_frac(j1) : 0.0f;

    const float MAGIC  = 12582912.0f;       // 1.5 * 2^23
    const float TWOPI  = 6.2831853f;
    const float C11 = -2.3889859e-08f;
    const float C9  =  2.7525562e-06f;
    const float C7  = -0.00019840874f;
    const float C5  =  0.0083333310f;
    const float C3  = -0.16666667f;

    float acc_a = 0.0f, acc_b = 0.0f;
#pragma unroll
    for (int k = 0; k < 64; k++) {
        // 7-of-32 poly pattern: {0,5,10,15,20,25,30} per 32 (measured optimum)
        bool poly = ((k & 31) % 5 == 0) && ((k & 31) != 31);
        if (poly) {
            // fma-pipe path: turns + magic reduce + deg-11 odd minimax
            float4 q = md1[k];
            float a0k = md0[k].w, dak = q.w;
            float ph = fmaf(t1a, q.y, q.x); ph = fmaf(F1a, q.z, ph);
            float kr = (ph + MAGIC) - MAGIC;        // rint(ph) in turns
            float r  = (ph - kr) * TWOPI;           // [-pi, pi] radians
            float x2 = r * r;
            float p  = fmaf(C11, x2, C9);
            p = fmaf(p, x2, C7); p = fmaf(p, x2, C5);
            p = fmaf(p, x2, C3); p = fmaf(p, x2, 1.0f);
            float aa = fmaf(dak, fra, a0k);
            acc_a = fmaf(aa * r, p, acc_a);
            float phb = fmaf(t1b, q.y, q.x); phb = fmaf(F1b, q.z, phb);
            float krb = (phb + MAGIC) - MAGIC;
            float rb  = (phb - krb) * TWOPI;
            float xb2 = rb * rb;
            float pb  = fmaf(C11, xb2, C9);
            pb = fmaf(pb, xb2, C7); pb = fmaf(pb, xb2, C5);
            pb = fmaf(pb, xb2, C3); pb = fmaf(pb, xb2, 1.0f);
            float ab = fmaf(dak, frb, a0k);
            acc_b = fmaf(ab * rb, pb, acc_b);
        } else {
            // MUFU path
            float4 q = md0[k];
            float dak = md1[k].w;
            float ph  = fmaf(t1a, q.y, q.x); ph  = fmaf(F1a, q.z, ph);
            float phb = fmaf(t1b, q.y, q.x); phb = fmaf(F1b, q.z, phb);
            float aa = fmaf(dak, fra, q.w);
            float ab = fmaf(dak, frb, q.w);
            acc_a = fmaf(aa, __sinf(ph),  acc_a);
            acc_b = fmaf(ab, __sinf(phb), acc_b);
        }
    }

    out[(size_t)b * NS + j0] = acc_a;
    if (interior) out[(size_t)b * NS + j1] = acc_b;
}

extern "C" void kernel_launch(void* const* d_in, const int* in_sizes, int n_in,
                              void* d_out, int out_size) {
    const float* params = (const float*)d_in[0];
    float* out = (float*)d_out;
    prep_kernel<<<PREP_BLOCKS, 128>>>(params);
    dim3 grid(NSEG, NB);
    synth_kernel<<<grid, 64>>>(params, out);
}

// round 16
// speedup vs baseline: 1.1410x; 1.1077x over previous
#include <cuda_runtime.h>

#define NS   48000
#define NIN  400
#define NSEG 401      // head(60) + 399 interior(120) + tail(60)
#define NB   16
#define NM   64
#define NROWS (NB*NM)

// ---------------------------------------------------------------------------
// Compile-time tables. The frac-cumsum table depends only on sample indices,
// never on inputs — so it is baked into the binary. constexpr float/double
// arithmetic is IEEE round-to-nearest with no FMA contraction, bit-matching
// the __fmul_rn/__fsub_rn sequence previously executed on device.
// ---------------------------------------------------------------------------
struct Tables {
    float  F1[NSEG * 120];   // inclusive frac-cumsum within each segment
    double FT[NSEG];         // total frac over the segment (interior: 120 samples)
};

static constexpr float ref_frac_h(int j) {
    constexpr float SCALE = 400.0f / 48000.0f;   // fl32(1/120)
    float pos = ((float)j + 0.5f) * SCALE - 0.5f;
    if (pos < 0.0f)   pos = 0.0f;
    if (pos > 399.0f) pos = 399.0f;
    float fi = (float)(int)pos;                  // trunc == floor (pos >= 0)
    return pos - fi;                             // exact (Sterbenz)
}

static constexpr Tables gen_tables() {
    Tables t{};
    for (int s = 0; s < NSEG; s++) {
        int cnt   = (s == 0 || s == 400) ? 60 : 120;
        int start = (s == 0) ? 0 : 60 + (s - 1) * 120;
        double acc = 0.0;
        for (int m = 0; m < cnt; m++) {
            acc += (double)ref_frac_h(start + m);
            t.F1[s * 120 + m] = (float)acc;
        }
        for (int m = cnt; m < 120; m++) t.F1[s * 120 + m] = 0.0f;
        t.FT[s] = acc;   // only read for interior segments (cnt == 120)
    }
    return t;
}

__device__ constexpr Tables c_tab = gen_tables();

// Scratch (allocation-free)
__device__ float2 g_Bp[(size_t)NROWS * NSEG];  // per-(row,seg) phase base {radians, turns}

// Runtime replica of the reference's fp32 position/frac computation
// (used per-sample in synth for the amplitude interpolation weight).
__device__ __forceinline__ float ref_frac(int j) {
    const float SCALE = 400.0f / 48000.0f;
    float pos = __fsub_rn(__fmul_rn(__fadd_rn((float)j, 0.5f), SCALE), 0.5f);
    pos = fminf(fmaxf(pos, 0.0f), 399.0f);
    float fi = floorf(pos);
    return __fsub_rn(pos, fi);
}

// Scan kernel (no dependencies): block = row; per-row fp64 exclusive prefix
// over segment sums, + phase[row][0], reduced mod 2pi, stored as
// {radians, turns} floats so synth setup is pure fp32.
__global__ void __launch_bounds__(128, 8)
scan_kernel(const float* __restrict__ params) {
    int tid  = threadIdx.x;
    int lane = tid & 31, wp = tid >> 5;
    int r = blockIdx.x;                 // 0..1023 : b*64 + mode
    int b = r >> 6, mode = r & 63;
    const float* F = params + (size_t)(b * 192 + mode) * 400;  // freqs
    const float* P = F + 128 * 400;                            // phase
    float p0 = P[0];

    double loc[4];
    double run = 0.0;
    #pragma unroll
    for (int i = 0; i < 4; i++) {
        int idx = tid * 4 + i;
        double v = 0.0;
        if (idx == 0) {
            v = 60.0 * (double)F[0];    // head: frac == 0 for all 60 samples
        } else if (idx <= 399) {
            double f0 = F[idx - 1], f1 = F[idx];
            v = 120.0 * f0 + (f1 - f0) * c_tab.FT[idx];
        }
        run += v;
        loc[i] = run;                   // local inclusive
    }
    // warp scan of thread totals
    double T = run, inc = T;
    #pragma unroll
    for (int off = 1; off < 32; off <<= 1) {
        double n = __shfl_up_sync(0xFFFFFFFFu, inc, off);
        if (lane >= off) inc += n;
    }
    __shared__ double sW[4];
    if (lane == 31) sW[wp] = inc;
    __syncthreads();
    double wbase = 0.0;
    #pragma unroll
    for (int i = 0; i < 3; i++)
        if (i < wp) wbase += sW[i];
    double tbase = wbase + (inc - T);

    #pragma unroll
    for (int i = 0; i < 4; i++) {
        int idx = tid * 4 + i;
        if (idx <= 400) {
            double excl = tbase + (i ? loc[i - 1] : 0.0);
            double tot  = excl + (double)p0;
            double tt   = tot * 0.15915494309189535;   // turns
            double kk   = rint(tt);
            double ft   = tt - kk;                     // [-0.5, 0.5] turns
            g_Bp[(size_t)r * NSEG + idx] =
                make_float2((float)(ft * 6.283185307179586), (float)ft);
        }
    }
}

// Synthesis: block=(segment s, batch b), 64 threads, 2 samples/thread.
// Measured-optimal hybrid (R9): 7 of every 32 modes via fma-pipe polynomial
// (turns phase, magic-rint reduce, deg-11 odd minimax), rest via MUFU.
__global__ void __launch_bounds__(64) synth_kernel(const float* __restrict__ params,
                                                   float* __restrict__ out) {
    int s = blockIdx.x, b = blockIdx.y;
    __shared__ float4 md0[64];   // {base_rad, f0_rad, dF_rad, a0}
    __shared__ float4 md1[64];   // {base_trn, f0_trn, dF_trn, da}
    int tid = threadIdx.x;

    {
        int mode = tid;          // 64 threads == 64 modes
        const float* F = params + (size_t)(b * 192 + mode) * 400;
        const float* A = F + 64 * 400;      // channel 1 = amps
        int i  = (s == 0) ? 0 : ((s <= 399) ? s - 1 : 399);
        int i1 = min(i + 1, 399);
        float f0 = F[i];
        float dw = F[i1] - f0;
        float a0 = A[i];
        float da = A[i1] - a0;
        float2 bp = g_Bp[(size_t)(b * 64 + mode) * NSEG + s];
        const float INV2PI_F = 0.15915494f;
        md0[mode] = make_float4(bp.x, f0, dw, a0);
        md1[mode] = make_float4(bp.y, f0 * INV2PI_F, dw * INV2PI_F, da);
    }
    __syncthreads();

    int m = tid;
    if (m >= 60) return;                    // 60 threads x 2 samples = 120
    bool interior = (s != 0 && s != 400);
    int start = (s == 0) ? 0 : 60 + (s - 1) * 120;
    int j0 = start + m;
    int j1 = start + m + 60;

    float t1a = (float)(m + 1),  t1b = (float)(m + 61);
    float F1a = c_tab.F1[s * 120 + m], F1b = c_tab.F1[s * 120 + m + 60];
    float fra = ref_frac(j0);
    float frb = interior ? ref_frac(j1) : 0.0f;

    const float MAGIC  = 12582912.0f;       // 1.5 * 2^23
    const float TWOPI  = 6.2831853f;
    const float C11 = -2.3889859e-08f;
    const float C9  =  2.7525562e-06f;
    const float C7  = -0.00019840874f;
    const float C5  =  0.0083333310f;
    const float C3  = -0.16666667f;

    float acc_a = 0.0f, acc_b = 0.0f;
#pragma unroll
    for (int k = 0; k < 64; k++) {
        // 7-of-32 poly pattern: {0,5,10,15,20,25,30} per 32 (measured optimum)
        bool poly = ((k & 31) % 5 == 0) && ((k & 31) != 31);
        if (poly) {
            // fma-pipe path: turns + magic reduce + deg-11 odd minimax
            float4 q = md1[k];
            float a0k = md0[k].w, dak = q.w;
            float ph = fmaf(t1a, q.y, q.x); ph = fmaf(F1a, q.z, ph);
            float kr = (ph + MAGIC) - MAGIC;        // rint(ph) in turns
            float r  = (ph - kr) * TWOPI;           // [-pi, pi] radians
            float x2 = r * r;
            float p  = fmaf(C11, x2, C9);
            p = fmaf(p, x2, C7); p = fmaf(p, x2, C5);
            p = fmaf(p, x2, C3); p = fmaf(p, x2, 1.0f);
            float aa = fmaf(dak, fra, a0k);
            acc_a = fmaf(aa * r, p, acc_a);
            float phb = fmaf(t1b, q.y, q.x); phb = fmaf(F1b, q.z, phb);
            float krb = (phb + MAGIC) - MAGIC;
            float rb  = (phb - krb) * TWOPI;
            float xb2 = rb * rb;
            float pb  = fmaf(C11, xb2, C9);
            pb = fmaf(pb, xb2, C7); pb = fmaf(pb, xb2, C5);
            pb = fmaf(pb, xb2, C3); pb = fmaf(pb, xb2, 1.0f);
            float ab = fmaf(dak, frb, a0k);
            acc_b = fmaf(ab * rb, pb, acc_b);
        } else {
            // MUFU path
            float4 q = md0[k];
            float dak = md1[k].w;
            float ph  = fmaf(t1a, q.y, q.x); ph  = fmaf(F1a, q.z, ph);
            float phb = fmaf(t1b, q.y, q.x); phb = fmaf(F1b, q.z, phb);
            float aa = fmaf(dak, fra, q.w);
            float ab = fmaf(dak, frb, q.w);
            acc_a = fmaf(aa, __sinf(ph),  acc_a);
            acc_b = fmaf(ab, __sinf(phb), acc_b);
        }
    }

    out[(size_t)b * NS + j0] = acc_a;
    if (interior) out[(size_t)b * NS + j1] = acc_b;
}

extern "C" void kernel_launch(void* const* d_in, const int* in_sizes, int n_in,
                              void* d_out, int out_size) {
    const float* params = (const float*)d_in[0];
    float* out = (float*)d_out;
    scan_kernel<<<NROWS, 128>>>(params);
    dim3 grid(NSEG, NB);
    synth_kernel<<<grid, 64>>>(params, out);
}